// round 5
// baseline (speedup 1.0000x reference)
#include <cuda_runtime.h>
#include <cuda_bf16.h>
#include <cstdint>
#include <math.h>

// Problem constants
#define M_DIM 16384          // B*S
#define K_DIM 4864           // IN_DIM
#define N_DIM 640            // G*V
#define NVARS 320
#define NGROUPS 2
#define CVD   128
#define MARGIN 0.02f

// GEMM tiling
#define BM 128
#define BN 128
#define BK 32
#define STAGES 3
#define NKT (K_DIM / BK)                 // 152

#define SM_A_STAGE (BM * BK * 2)         // 8 KB
#define SM_B_STAGE (BN * BK * 2)         // 8 KB
#define SM_STAGE   (SM_A_STAGE + SM_B_STAGE)
#define SM_TOTAL   (STAGES * SM_STAGE)   // 48 KB -> 2 CTAs/SM = 96 KB

// ---------------- scratch ----------------
__device__ __nv_bfloat16 g_Btbf[(size_t)N_DIM * K_DIM];  // ~6.2 MB  W^T bf16 [n][k]
__device__ float         g_Wt[(size_t)N_DIM * K_DIM];    // ~12.5 MB W^T fp32 [n][k]
__device__ float         g_logits[(size_t)M_DIM * N_DIM];// ~42 MB
__device__ int           g_idx[M_DIM * NGROUPS];
__device__ int           g_counts[N_DIM];

// ---------------- helpers ----------------
__device__ __forceinline__ uint32_t smem_u32(const void* p) {
    uint32_t a;
    asm("{ .reg .u64 t; cvta.to.shared.u64 t, %1; cvt.u32.u64 %0, t; }" : "=r"(a) : "l"(p));
    return a;
}
__device__ __forceinline__ void ldsm_x4(uint32_t* r, uint32_t addr) {
    asm volatile("ldmatrix.sync.aligned.m8n8.x4.shared.b16 {%0,%1,%2,%3}, [%4];"
        : "=r"(r[0]), "=r"(r[1]), "=r"(r[2]), "=r"(r[3]) : "r"(addr));
}
// stage offset for (logical row r in 0..127, 16B chunk c in 0..3 of a 32-col row)
// superrow s = r>>1 holds two rows (128B); j = (r&1)*4 + c; XOR swizzle on j.
__device__ __forceinline__ uint32_t stage_off(int r, int c) {
    int s = r >> 1;
    int j = ((r & 1) << 2) + c;
    return (uint32_t)(s * 128 + ((j ^ (s & 7)) << 4));
}

// ---------------- kernel: transpose W [K][N] -> Wt [N][K] (fp32 + bf16), half-K per launch ----------------
__global__ void trans_w_kernel(const float* __restrict__ W, int k_base) {
    __shared__ float tile[32][33];
    int x = blockIdx.x * 32 + threadIdx.x;
    int y0 = k_base + blockIdx.y * 32;
    #pragma unroll
    for (int j = threadIdx.y; j < 32; j += 8)
        tile[j][threadIdx.x] = W[(size_t)(y0 + j) * N_DIM + x];
    __syncthreads();
    #pragma unroll
    for (int j = threadIdx.y; j < 32; j += 8) {
        int n = blockIdx.x * 32 + j;
        int k = y0 + threadIdx.x;
        float val = tile[threadIdx.x][j];
        g_Wt[(size_t)n * K_DIM + k] = val;
        g_Btbf[(size_t)n * K_DIM + k] = __float2bfloat16_rn(val);
    }
}

// ---------------- zero counts ----------------
__global__ void zero_counts_kernel() { g_counts[threadIdx.x] = 0; }

// ---------------- fused GEMM: logits = fp32A @ bf16(W^T) + b ----------------
// CTA 128x128, BK=32, 3 stages. A: LDG.128 fp32 -> cvt -> STS bf16 (reg-pipelined).
// B: cp.async bf16. 8 warps (4Mx2N), warp tile 32x64, 2 CTAs/SM.
__global__ __launch_bounds__(256, 2) void gemm_kernel(const float* __restrict__ A,
                                                      const float* __restrict__ bias) {
    extern __shared__ char smem[];
    const uint32_t su = smem_u32(smem);
    const int tid  = threadIdx.x;
    const int lane = tid & 31;
    const int warp = tid >> 5;
    const int wm = warp >> 1;
    const int wn = warp & 1;
    const int cta_m = blockIdx.y * BM;
    const int cta_n = blockIdx.x * BN;

    float acc[2][8][4];
    #pragma unroll
    for (int a = 0; a < 2; a++)
        #pragma unroll
        for (int b = 0; b < 8; b++)
            #pragma unroll
            for (int c = 0; c < 4; c++) acc[a][b][c] = 0.0f;

    // ---- per-thread loader indices ----
    // A: idx = tid + 256*i (i<4) over 1024 float4; row = idx>>3, c4 = idx&7
    // B: idx = tid + 256*i (i<2) over 512 16B-chunks; row = idx>>2, c = idx&3
    const float* Ag = A + (size_t)cta_m * K_DIM;
    const __nv_bfloat16* Bg = g_Btbf + (size_t)cta_n * K_DIM;

    float4 pf[4];   // A prefetch registers (one stage ahead)

    auto ldg_a = [&](int kt) {
        const int k0 = kt * BK;
        #pragma unroll
        for (int i = 0; i < 4; i++) {
            int idx = tid + 256 * i;
            int row = idx >> 3, c4 = idx & 7;
            pf[i] = *reinterpret_cast<const float4*>(Ag + (size_t)row * K_DIM + k0 + c4 * 4);
        }
    };
    auto sts_a = [&](int kt) {
        const uint32_t aB = su + (kt % STAGES) * SM_STAGE;
        #pragma unroll
        for (int i = 0; i < 4; i++) {
            int idx = tid + 256 * i;
            int row = idx >> 3, c4 = idx & 7;
            uint32_t dst = aB + stage_off(row, c4 >> 1) + (c4 & 1) * 8;
            __nv_bfloat162 lo = __floats2bfloat162_rn(pf[i].x, pf[i].y);
            __nv_bfloat162 hi = __floats2bfloat162_rn(pf[i].z, pf[i].w);
            uint32_t r0 = *reinterpret_cast<uint32_t*>(&lo);
            uint32_t r1 = *reinterpret_cast<uint32_t*>(&hi);
            asm volatile("st.shared.v2.b32 [%0], {%1, %2};" :: "r"(dst), "r"(r0), "r"(r1));
        }
    };
    auto cp_b = [&](int kt) {
        const int k0 = kt * BK;
        const uint32_t bB = su + (kt % STAGES) * SM_STAGE + SM_A_STAGE;
        #pragma unroll
        for (int i = 0; i < 2; i++) {
            int idx = tid + 256 * i;
            int row = idx >> 2, c = idx & 3;
            uint32_t dst = bB + stage_off(row, c);
            const void* src = Bg + (size_t)row * K_DIM + k0 + c * 8;
            asm volatile("cp.async.cg.shared.global [%0], [%1], 16;" :: "r"(dst), "l"(src));
        }
    };

    // ---- fragment smem offsets ----
    const int aRow0 = wm * 32 + (lane & 15);            // + mt*16
    const int aCHi  = lane >> 4;                         // chunk = kk*2 + aCHi
    const int bRow0 = wn * 64 + ((lane >> 4) << 3) + (lane & 7);  // + p*16
    const int bCHi  = (lane >> 3) & 1;

    // ---- preamble ----
    ldg_a(0);
    cp_b(0); asm volatile("cp.async.commit_group;");
    cp_b(1); asm volatile("cp.async.commit_group;");
    sts_a(0);
    ldg_a(1);

    for (int kt = 0; kt < NKT; kt++) {
        if (kt < NKT - 1) asm volatile("cp.async.wait_group 1;");
        else              asm volatile("cp.async.wait_group 0;");
        __syncthreads();

        if (kt + 1 < NKT) sts_a(kt + 1);
        if (kt + 2 < NKT) {
            ldg_a(kt + 2);
            cp_b(kt + 2);
            asm volatile("cp.async.commit_group;");
        }

        const uint32_t stBase = su + (kt % STAGES) * SM_STAGE;
        const uint32_t bBase  = stBase + SM_A_STAGE;

        #pragma unroll
        for (int kk = 0; kk < 2; kk++) {
            uint32_t afr[2][4];
            #pragma unroll
            for (int mt = 0; mt < 2; mt++)
                ldsm_x4(afr[mt], stBase + stage_off(aRow0 + mt * 16, kk * 2 + aCHi));
            uint32_t bfr[4][4];
            #pragma unroll
            for (int p = 0; p < 4; p++)
                ldsm_x4(bfr[p], bBase + stage_off(bRow0 + p * 16, kk * 2 + bCHi));
            #pragma unroll
            for (int mt = 0; mt < 2; mt++) {
                #pragma unroll
                for (int p = 0; p < 4; p++) {
                    asm volatile(
                        "mma.sync.aligned.m16n8k16.row.col.f32.bf16.bf16.f32 "
                        "{%0,%1,%2,%3}, {%4,%5,%6,%7}, {%8,%9}, {%0,%1,%2,%3};\n"
                        : "+f"(acc[mt][2*p][0]), "+f"(acc[mt][2*p][1]),
                          "+f"(acc[mt][2*p][2]), "+f"(acc[mt][2*p][3])
                        : "r"(afr[mt][0]), "r"(afr[mt][1]), "r"(afr[mt][2]), "r"(afr[mt][3]),
                          "r"(bfr[p][0]), "r"(bfr[p][1]));
                    asm volatile(
                        "mma.sync.aligned.m16n8k16.row.col.f32.bf16.bf16.f32 "
                        "{%0,%1,%2,%3}, {%4,%5,%6,%7}, {%8,%9}, {%0,%1,%2,%3};\n"
                        : "+f"(acc[mt][2*p+1][0]), "+f"(acc[mt][2*p+1][1]),
                          "+f"(acc[mt][2*p+1][2]), "+f"(acc[mt][2*p+1][3])
                        : "r"(afr[mt][0]), "r"(afr[mt][1]), "r"(afr[mt][2]), "r"(afr[mt][3]),
                          "r"(bfr[p][2]), "r"(bfr[p][3]));
                }
            }
        }
    }

    // epilogue
    const int g = lane >> 2;
    const int t = lane & 3;
    #pragma unroll
    for (int mt = 0; mt < 2; mt++) {
        int row = cta_m + wm * 32 + mt * 16 + g;
        #pragma unroll
        for (int nt = 0; nt < 8; nt++) {
            int col = cta_n + wn * 64 + nt * 8 + 2 * t;
            float2 bv = *reinterpret_cast<const float2*>(bias + col);
            float2 v0 = make_float2(acc[mt][nt][0] + bv.x, acc[mt][nt][1] + bv.y);
            float2 v1 = make_float2(acc[mt][nt][2] + bv.x, acc[mt][nt][3] + bv.y);
            *reinterpret_cast<float2*>(g_logits + (size_t)row * N_DIM + col) = v0;
            *reinterpret_cast<float2*>(g_logits + (size_t)(row + 8) * N_DIM + col) = v1;
        }
    }
}

// ---------------- argmax + exact fp32 rescue + histogram ----------------
__global__ __launch_bounds__(256) void argmax_kernel(const float* __restrict__ hidden,
                                                     const float* __restrict__ bias) {
    const int lane = threadIdx.x & 31;
    const int gw = blockIdx.x * 8 + (threadIdx.x >> 5);
    const int r = gw >> 1;
    const int g = gw & 1;
    const float* base = g_logits + (size_t)r * N_DIM + g * NVARS;

    float v[10];
    float bestv = -INFINITY;
    int besti = 0x7fffffff;
    #pragma unroll
    for (int j = 0; j < 10; j++) {
        v[j] = base[lane + 32 * j];
        int idx = lane + 32 * j;
        if (v[j] > bestv) { bestv = v[j]; besti = idx; }
    }
    #pragma unroll
    for (int off = 16; off > 0; off >>= 1) {
        float ov = __shfl_down_sync(0xffffffffu, bestv, off);
        int   oi = __shfl_down_sync(0xffffffffu, besti, off);
        if (ov > bestv || (ov == bestv && oi < besti)) { bestv = ov; besti = oi; }
    }
    bestv = __shfl_sync(0xffffffffu, bestv, 0);
    besti = __shfl_sync(0xffffffffu, besti, 0);

    const float thr = bestv - MARGIN;
    unsigned masks[10];
    int ncand = 0;
    #pragma unroll
    for (int j = 0; j < 10; j++) {
        masks[j] = __ballot_sync(0xffffffffu, v[j] >= thr);
        ncand += __popc(masks[j]);
    }

    int final_idx = besti;
    if (ncand > 1) {
        const float* hrow = hidden + (size_t)r * K_DIM;
        float bexact = -INFINITY;
        int bidx = -1;
        for (int j = 0; j < 10; j++) {
            unsigned m = masks[j];
            while (m) {
                int l = __ffs(m) - 1;
                m &= m - 1;
                int col = l + 32 * j;
                const float* wrow = g_Wt + (size_t)(g * NVARS + col) * K_DIM;
                float s = 0.0f;
                for (int k = lane; k < K_DIM; k += 32)
                    s = fmaf(hrow[k], wrow[k], s);
                #pragma unroll
                for (int off = 16; off > 0; off >>= 1)
                    s += __shfl_xor_sync(0xffffffffu, s, off);
                s += bias[g * NVARS + col];
                if (s > bexact) { bexact = s; bidx = col; }
            }
        }
        final_idx = bidx;
    }

    if (lane == 0) {
        g_idx[r * 2 + g] = final_idx;
        atomicAdd(&g_counts[g * NVARS + final_idx], 1);
    }
}

// ---------------- gather codevectors ----------------
__global__ void gather_kernel(const float* __restrict__ cv, float* __restrict__ out) {
    int gid = blockIdx.x * blockDim.x + threadIdx.x;
    int r = gid >> 6;
    int q = gid & 63;
    int d = q * 4;
    const float* src;
    if (d < CVD) {
        int i0 = g_idx[r * 2];
        src = cv + ((size_t)i0 * CVD + d);
    } else {
        int i1 = g_idx[r * 2 + 1];
        src = cv + ((size_t)(NVARS + i1) * CVD + (d - CVD));
    }
    float4 val = *reinterpret_cast<const float4*>(src);
    *reinterpret_cast<float4*>(out + (size_t)r * 256 + d) = val;
}

// ---------------- perplexity ----------------
__global__ void ppl_kernel(float* __restrict__ out_scalar) {
    __shared__ float wsum[20];
    int tid = threadIdx.x;
    float m = (float)g_counts[tid] * (1.0f / 16384.0f);
    float term = m * logf(m + 1e-7f);
    #pragma unroll
    for (int off = 16; off > 0; off >>= 1)
        term += __shfl_xor_sync(0xffffffffu, term, off);
    if ((tid & 31) == 0) wsum[tid >> 5] = term;
    __syncthreads();
    if (tid == 0) {
        float s0 = 0.0f, s1 = 0.0f;
        #pragma unroll
        for (int w = 0; w < 10; w++) s0 += wsum[w];
        #pragma unroll
        for (int w = 10; w < 20; w++) s1 += wsum[w];
        *out_scalar = expf(-s0) + expf(-s1);
    }
}

// ---------------- launch ----------------
extern "C" void kernel_launch(void* const* d_in, const int* in_sizes, int n_in,
                              void* d_out, int out_size) {
    const float* hidden = (const float*)d_in[0];
    const float* W      = (const float*)d_in[1];
    const float* bias   = (const float*)d_in[2];
    const float* cv     = (const float*)d_in[3];
    float* out = (float*)d_out;

    cudaFuncSetAttribute(gemm_kernel, cudaFuncAttributeMaxDynamicSharedMemorySize, SM_TOTAL);

    // launch order puts gemm 4th -> ncu's deterministic skip profiles it
    trans_w_kernel<<<dim3(N_DIM / 32, K_DIM / 64), dim3(32, 8)>>>(W, 0);
    trans_w_kernel<<<dim3(N_DIM / 32, K_DIM / 64), dim3(32, 8)>>>(W, K_DIM / 2);
    zero_counts_kernel<<<1, N_DIM>>>();
    gemm_kernel<<<dim3(N_DIM / BN, M_DIM / BM), 256, SM_TOTAL>>>(hidden, bias);
    argmax_kernel<<<(M_DIM * NGROUPS) / 8, 256>>>(hidden, bias);
    gather_kernel<<<(M_DIM * 64) / 256, 256>>>(cv, out);
    ppl_kernel<<<1, N_DIM>>>(out + (out_size - 1));
}

// round 6
// speedup vs baseline: 1.6349x; 1.6349x over previous
#include <cuda_runtime.h>
#include <cuda_bf16.h>
#include <cstdint>
#include <math.h>

// Problem constants
#define M_DIM 16384          // B*S
#define K_DIM 4864           // IN_DIM
#define N_DIM 640            // G*V
#define NVARS 320
#define NGROUPS 2
#define CVD   128
#define MARGIN 0.02f

// GEMM tiling
#define BM 128
#define BN 128
#define BK 64
#define STAGES 3
#define NKT (K_DIM / BK)                 // 76

#define SM_A_STAGE (BM * BK * 2)         // 16 KB
#define SM_B_STAGE (BN * BK * 2)         // 16 KB
#define SM_STAGE   (SM_A_STAGE + SM_B_STAGE)
#define SM_TOTAL   (STAGES * SM_STAGE)   // 96 KB -> 2 CTAs/SM

// ---------------- scratch ----------------
__device__ __nv_bfloat16 g_Abf[(size_t)M_DIM * K_DIM];   // ~159 MB
__device__ __nv_bfloat16 g_Btbf[(size_t)N_DIM * K_DIM];  // ~6.2 MB  W^T bf16 [n][k]
__device__ float         g_Wt[(size_t)N_DIM * K_DIM];    // ~12.5 MB W^T fp32 [n][k]
__device__ float         g_logits[(size_t)M_DIM * N_DIM];// ~42 MB
__device__ int           g_idx[M_DIM * NGROUPS];
__device__ int           g_counts[N_DIM];

// ---------------- helpers ----------------
__device__ __forceinline__ uint32_t smem_u32(const void* p) {
    uint32_t a;
    asm("{ .reg .u64 t; cvta.to.shared.u64 t, %1; cvt.u32.u64 %0, t; }" : "=r"(a) : "l"(p));
    return a;
}
__device__ __forceinline__ void ldsm_x4(uint32_t* r, uint32_t addr) {
    asm volatile("ldmatrix.sync.aligned.m8n8.x4.shared.b16 {%0,%1,%2,%3}, [%4];"
        : "=r"(r[0]), "=r"(r[1]), "=r"(r[2]), "=r"(r[3]) : "r"(addr));
}

// ---------------- kernel 1a/1b: convert hidden_states fp32 -> bf16 (half per launch) ----------------
__global__ void conv_a_kernel(const float* __restrict__ A, int base) {
    int i = base + blockIdx.x * blockDim.x + threadIdx.x;
    float4 v = reinterpret_cast<const float4*>(A)[i];
    __nv_bfloat162* o = reinterpret_cast<__nv_bfloat162*>(g_Abf) + (size_t)i * 2;
    o[0] = __floats2bfloat162_rn(v.x, v.y);
    o[1] = __floats2bfloat162_rn(v.z, v.w);
}

// ---------------- kernel 2: transpose W + zero counts ----------------
// grid (20, 152), 256 threads mapped as (32, 8)
__global__ void trans_w_kernel(const float* __restrict__ W) {
    __shared__ float tile[32][33];
    const int tx = threadIdx.x & 31;
    const int ty = threadIdx.x >> 5;
    if (blockIdx.x == 0 && blockIdx.y == 0) {
        for (int i = threadIdx.x; i < N_DIM; i += 256) g_counts[i] = 0;
    }
    int x = blockIdx.x * 32 + tx;
    int y0 = blockIdx.y * 32;
    #pragma unroll
    for (int j = ty; j < 32; j += 8)
        tile[j][tx] = W[(size_t)(y0 + j) * N_DIM + x];
    __syncthreads();
    #pragma unroll
    for (int j = ty; j < 32; j += 8) {
        int n = blockIdx.x * 32 + j;
        int k = y0 + tx;
        float val = tile[tx][j];
        g_Wt[(size_t)n * K_DIM + k] = val;
        g_Btbf[(size_t)n * K_DIM + k] = __float2bfloat16_rn(val);
    }
}

// ---------------- kernel 3: bf16 HMMA GEMM, logits = A @ W^T + b ----------------
// CTA 128x128, BK=64, 3-stage cp.async, ldmatrix fragments, 8 warps (4Mx2N),
// warp tile 32x64, 2 CTAs/SM, ONE barrier per K-step.
__global__ __launch_bounds__(256, 2) void gemm_kernel(const float* __restrict__ bias) {
    extern __shared__ char smem[];
    const uint32_t su = smem_u32(smem);
    const int tid  = threadIdx.x;
    const int lane = tid & 31;
    const int warp = tid >> 5;
    const int wm = warp >> 1;        // 0..3
    const int wn = warp & 1;         // 0..1
    const int cta_m = blockIdx.y * BM;
    const int cta_n = blockIdx.x * BN;

    float acc[2][8][4];
    #pragma unroll
    for (int a = 0; a < 2; a++)
        #pragma unroll
        for (int b = 0; b < 8; b++)
            #pragma unroll
            for (int c = 0; c < 4; c++) acc[a][b][c] = 0.0f;

    // ---- fragment smem offsets (128B rows; swizzle: chunk ^= row&7) ----
    const int sw = lane & 7;
    uint32_t aOff[2];
    #pragma unroll
    for (int mt = 0; mt < 2; mt++)
        aOff[mt] = (uint32_t)((wm * 32 + mt * 16 + (lane & 15)) * 128);
    const int aChunkHi = lane >> 4;
    uint32_t bOff[4];
    #pragma unroll
    for (int p = 0; p < 4; p++)
        bOff[p] = (uint32_t)((wn * 64 + p * 16 + ((lane >> 4) << 3) + (lane & 7)) * 128);
    const int bChunkHi = (lane >> 3) & 1;

    // ---- stage loader: 16B cp.async, swizzled ----
    const __nv_bfloat16* Ag = g_Abf + (size_t)cta_m * K_DIM;
    const __nv_bfloat16* Bg = g_Btbf + (size_t)cta_n * K_DIM;
    auto load_stage = [&](int kt) {
        const int st = kt % STAGES;
        const int k0 = kt * BK;
        const uint32_t aB = su + st * SM_STAGE;
        const uint32_t bB = aB + SM_A_STAGE;
        #pragma unroll
        for (int i = 0; i < 4; i++) {
            int ch = tid + 256 * i;
            int row = ch >> 3, c = ch & 7;
            uint32_t dst = aB + row * 128 + ((c ^ (row & 7)) << 4);
            const void* src = Ag + (size_t)row * K_DIM + k0 + c * 8;
            asm volatile("cp.async.cg.shared.global [%0], [%1], 16;" :: "r"(dst), "l"(src));
        }
        #pragma unroll
        for (int i = 0; i < 4; i++) {
            int ch = tid + 256 * i;
            int row = ch >> 3, c = ch & 7;
            uint32_t dst = bB + row * 128 + ((c ^ (row & 7)) << 4);
            const void* src = Bg + (size_t)row * K_DIM + k0 + c * 8;
            asm volatile("cp.async.cg.shared.global [%0], [%1], 16;" :: "r"(dst), "l"(src));
        }
    };

    load_stage(0); asm volatile("cp.async.commit_group;");
    load_stage(1); asm volatile("cp.async.commit_group;");

    for (int kt = 0; kt < NKT; kt++) {
        if (kt + 1 < NKT) asm volatile("cp.async.wait_group 1;");
        else              asm volatile("cp.async.wait_group 0;");
        __syncthreads();   // single barrier: orders stage-kt visibility AND protects
                           // stage (kt-1)%3 (== (kt+2)%3) from overwrite below

        if (kt + 2 < NKT) { load_stage(kt + 2); asm volatile("cp.async.commit_group;"); }

        const uint32_t stBase = su + (kt % STAGES) * SM_STAGE;
        const uint32_t bBase  = stBase + SM_A_STAGE;

        #pragma unroll
        for (int kk = 0; kk < 4; kk++) {
            uint32_t afr[2][4];
            #pragma unroll
            for (int mt = 0; mt < 2; mt++) {
                uint32_t addr = stBase + aOff[mt] + (((kk * 2 + aChunkHi) ^ sw) << 4);
                ldsm_x4(afr[mt], addr);
            }
            uint32_t bfr[4][4];
            #pragma unroll
            for (int p = 0; p < 4; p++) {
                uint32_t addr = bBase + bOff[p] + (((kk * 2 + bChunkHi) ^ sw) << 4);
                ldsm_x4(bfr[p], addr);
            }
            #pragma unroll
            for (int mt = 0; mt < 2; mt++) {
                #pragma unroll
                for (int p = 0; p < 4; p++) {
                    asm volatile(
                        "mma.sync.aligned.m16n8k16.row.col.f32.bf16.bf16.f32 "
                        "{%0,%1,%2,%3}, {%4,%5,%6,%7}, {%8,%9}, {%0,%1,%2,%3};\n"
                        : "+f"(acc[mt][2*p][0]), "+f"(acc[mt][2*p][1]),
                          "+f"(acc[mt][2*p][2]), "+f"(acc[mt][2*p][3])
                        : "r"(afr[mt][0]), "r"(afr[mt][1]), "r"(afr[mt][2]), "r"(afr[mt][3]),
                          "r"(bfr[p][0]), "r"(bfr[p][1]));
                    asm volatile(
                        "mma.sync.aligned.m16n8k16.row.col.f32.bf16.bf16.f32 "
                        "{%0,%1,%2,%3}, {%4,%5,%6,%7}, {%8,%9}, {%0,%1,%2,%3};\n"
                        : "+f"(acc[mt][2*p+1][0]), "+f"(acc[mt][2*p+1][1]),
                          "+f"(acc[mt][2*p+1][2]), "+f"(acc[mt][2*p+1][3])
                        : "r"(afr[mt][0]), "r"(afr[mt][1]), "r"(afr[mt][2]), "r"(afr[mt][3]),
                          "r"(bfr[p][2]), "r"(bfr[p][3]));
                }
            }
        }
    }

    // epilogue: add bias, write logits
    const int g = lane >> 2;
    const int t = lane & 3;
    #pragma unroll
    for (int mt = 0; mt < 2; mt++) {
        int row = cta_m + wm * 32 + mt * 16 + g;
        #pragma unroll
        for (int nt = 0; nt < 8; nt++) {
            int col = cta_n + wn * 64 + nt * 8 + 2 * t;
            float2 bv = *reinterpret_cast<const float2*>(bias + col);
            float2 v0 = make_float2(acc[mt][nt][0] + bv.x, acc[mt][nt][1] + bv.y);
            float2 v1 = make_float2(acc[mt][nt][2] + bv.x, acc[mt][nt][3] + bv.y);
            *reinterpret_cast<float2*>(g_logits + (size_t)row * N_DIM + col) = v0;
            *reinterpret_cast<float2*>(g_logits + (size_t)(row + 8) * N_DIM + col) = v1;
        }
    }
}

// ---------------- kernel 4: argmax + exact fp32 rescue + histogram ----------------
__global__ __launch_bounds__(256) void argmax_kernel(const float* __restrict__ hidden,
                                                     const float* __restrict__ bias) {
    const int lane = threadIdx.x & 31;
    const int gw = blockIdx.x * 8 + (threadIdx.x >> 5);
    const int r = gw >> 1;
    const int g = gw & 1;
    const float* base = g_logits + (size_t)r * N_DIM + g * NVARS;

    float v[10];
    float bestv = -INFINITY;
    int besti = 0x7fffffff;
    #pragma unroll
    for (int j = 0; j < 10; j++) {
        v[j] = base[lane + 32 * j];
        int idx = lane + 32 * j;
        if (v[j] > bestv) { bestv = v[j]; besti = idx; }
    }
    #pragma unroll
    for (int off = 16; off > 0; off >>= 1) {
        float ov = __shfl_down_sync(0xffffffffu, bestv, off);
        int   oi = __shfl_down_sync(0xffffffffu, besti, off);
        if (ov > bestv || (ov == bestv && oi < besti)) { bestv = ov; besti = oi; }
    }
    bestv = __shfl_sync(0xffffffffu, bestv, 0);
    besti = __shfl_sync(0xffffffffu, besti, 0);

    const float thr = bestv - MARGIN;
    unsigned masks[10];
    int ncand = 0;
    #pragma unroll
    for (int j = 0; j < 10; j++) {
        masks[j] = __ballot_sync(0xffffffffu, v[j] >= thr);
        ncand += __popc(masks[j]);
    }

    int final_idx = besti;
    if (ncand > 1) {
        const float* hrow = hidden + (size_t)r * K_DIM;
        float bexact = -INFINITY;
        int bidx = -1;
        for (int j = 0; j < 10; j++) {
            unsigned m = masks[j];
            while (m) {
                int l = __ffs(m) - 1;
                m &= m - 1;
                int col = l + 32 * j;
                const float* wrow = g_Wt + (size_t)(g * NVARS + col) * K_DIM;
                float s = 0.0f;
                for (int k = lane; k < K_DIM; k += 32)
                    s = fmaf(hrow[k], wrow[k], s);
                #pragma unroll
                for (int off = 16; off > 0; off >>= 1)
                    s += __shfl_xor_sync(0xffffffffu, s, off);
                s += bias[g * NVARS + col];
                if (s > bexact) { bexact = s; bidx = col; }
            }
        }
        final_idx = bidx;
    }

    if (lane == 0) {
        g_idx[r * 2 + g] = final_idx;
        atomicAdd(&g_counts[g * NVARS + final_idx], 1);
    }
}

// ---------------- kernel 5: gather codevectors ----------------
__global__ void gather_kernel(const float* __restrict__ cv, float* __restrict__ out) {
    int gid = blockIdx.x * blockDim.x + threadIdx.x;
    int r = gid >> 6;
    int q = gid & 63;
    int d = q * 4;
    const float* src;
    if (d < CVD) {
        int i0 = g_idx[r * 2];
        src = cv + ((size_t)i0 * CVD + d);
    } else {
        int i1 = g_idx[r * 2 + 1];
        src = cv + ((size_t)(NVARS + i1) * CVD + (d - CVD));
    }
    float4 val = *reinterpret_cast<const float4*>(src);
    *reinterpret_cast<float4*>(out + (size_t)r * 256 + d) = val;
}

// ---------------- kernel 6: perplexity ----------------
__global__ void ppl_kernel(float* __restrict__ out_scalar) {
    __shared__ float wsum[20];
    int tid = threadIdx.x;
    float m = (float)g_counts[tid] * (1.0f / 16384.0f);
    float term = m * logf(m + 1e-7f);
    #pragma unroll
    for (int off = 16; off > 0; off >>= 1)
        term += __shfl_xor_sync(0xffffffffu, term, off);
    if ((tid & 31) == 0) wsum[tid >> 5] = term;
    __syncthreads();
    if (tid == 0) {
        float s0 = 0.0f, s1 = 0.0f;
        #pragma unroll
        for (int w = 0; w < 10; w++) s0 += wsum[w];
        #pragma unroll
        for (int w = 10; w < 20; w++) s1 += wsum[w];
        *out_scalar = expf(-s0) + expf(-s1);
    }
}

// ---------------- launch ----------------
extern "C" void kernel_launch(void* const* d_in, const int* in_sizes, int n_in,
                              void* d_out, int out_size) {
    const float* hidden = (const float*)d_in[0];
    const float* W      = (const float*)d_in[1];
    const float* bias   = (const float*)d_in[2];
    const float* cv     = (const float*)d_in[3];
    float* out = (float*)d_out;

    cudaFuncSetAttribute(gemm_kernel, cudaFuncAttributeMaxDynamicSharedMemorySize, SM_TOTAL);

    const int convBlocks = (M_DIM * (K_DIM / 4)) / 256;    // 77824 total float4-blocks
    // gemm kept as the 4th launch: ncu's deterministic skip profiles it
    conv_a_kernel<<<convBlocks / 2, 256>>>(hidden, 0);
    conv_a_kernel<<<convBlocks / 2, 256>>>(hidden, (convBlocks / 2) * 256);
    trans_w_kernel<<<dim3(N_DIM / 32, K_DIM / 32), 256>>>(W);
    gemm_kernel<<<dim3(N_DIM / BN, M_DIM / BM), 256, SM_TOTAL>>>(bias);
    argmax_kernel<<<(M_DIM * NGROUPS) / 8, 256>>>(hidden, bias);
    gather_kernel<<<(M_DIM * 64) / 256, 256>>>(cv, out);
    ppl_kernel<<<1, N_DIM>>>(out + (out_size - 1));
}

// round 7
// speedup vs baseline: 1.7124x; 1.0474x over previous
#include <cuda_runtime.h>
#include <cuda_bf16.h>
#include <cstdint>
#include <math.h>

// Problem constants
#define M_DIM 16384          // B*S
#define K_DIM 4864           // IN_DIM
#define N_DIM 640            // G*V
#define NVARS 320
#define NGROUPS 2
#define CVD   128
#define MARGIN 0.02f

// GEMM tiling: CTA 128x64, 4 warps (2Mx2N), warp tile 64x32, 3 CTAs/SM
#define BM 128
#define BN 64
#define BK 64
#define STAGES 3
#define NKT (K_DIM / BK)                 // 76

#define SM_A_STAGE (BM * BK * 2)         // 16 KB
#define SM_B_STAGE (BN * BK * 2)         // 8 KB
#define SM_STAGE   (SM_A_STAGE + SM_B_STAGE)  // 24 KB
#define SM_TOTAL   (STAGES * SM_STAGE)   // 72 KB -> 3 CTAs/SM = 216 KB

// ---------------- scratch ----------------
__device__ __nv_bfloat16 g_Abf[(size_t)M_DIM * K_DIM];   // ~159 MB
__device__ __nv_bfloat16 g_Btbf[(size_t)N_DIM * K_DIM];  // ~6.2 MB  W^T bf16 [n][k]
__device__ float         g_Wt[(size_t)N_DIM * K_DIM];    // ~12.5 MB W^T fp32 [n][k]
__device__ float         g_logits[(size_t)M_DIM * N_DIM];// ~42 MB
__device__ int           g_idx[M_DIM * NGROUPS];
__device__ int           g_counts[N_DIM];

// ---------------- helpers ----------------
__device__ __forceinline__ uint32_t smem_u32(const void* p) {
    uint32_t a;
    asm("{ .reg .u64 t; cvta.to.shared.u64 t, %1; cvt.u32.u64 %0, t; }" : "=r"(a) : "l"(p));
    return a;
}
__device__ __forceinline__ void ldsm_x4(uint32_t* r, uint32_t addr) {
    asm volatile("ldmatrix.sync.aligned.m8n8.x4.shared.b16 {%0,%1,%2,%3}, [%4];"
        : "=r"(r[0]), "=r"(r[1]), "=r"(r[2]), "=r"(r[3]) : "r"(addr));
}

// ---------------- kernel 1a/1b: convert hidden_states fp32 -> bf16 (half per launch) ----------------
__global__ void conv_a_kernel(const float* __restrict__ A, int base) {
    int i = base + blockIdx.x * blockDim.x + threadIdx.x;
    float4 v = reinterpret_cast<const float4*>(A)[i];
    __nv_bfloat162* o = reinterpret_cast<__nv_bfloat162*>(g_Abf) + (size_t)i * 2;
    o[0] = __floats2bfloat162_rn(v.x, v.y);
    o[1] = __floats2bfloat162_rn(v.z, v.w);
}

// ---------------- kernel 2: transpose W + zero counts ----------------
__global__ void trans_w_kernel(const float* __restrict__ W) {
    __shared__ float tile[32][33];
    const int tx = threadIdx.x & 31;
    const int ty = threadIdx.x >> 5;
    if (blockIdx.x == 0 && blockIdx.y == 0) {
        for (int i = threadIdx.x; i < N_DIM; i += 256) g_counts[i] = 0;
    }
    int x = blockIdx.x * 32 + tx;
    int y0 = blockIdx.y * 32;
    #pragma unroll
    for (int j = ty; j < 32; j += 8)
        tile[j][tx] = W[(size_t)(y0 + j) * N_DIM + x];
    __syncthreads();
    #pragma unroll
    for (int j = ty; j < 32; j += 8) {
        int n = blockIdx.x * 32 + j;
        int k = y0 + tx;
        float val = tile[tx][j];
        g_Wt[(size_t)n * K_DIM + k] = val;
        g_Btbf[(size_t)n * K_DIM + k] = __float2bfloat16_rn(val);
    }
}

// ---------------- kernel 3: bf16 HMMA GEMM, logits = A @ W^T + b ----------------
// CTA 128x64, BK=64, 3-stage cp.async, ldmatrix fragments, 4 warps (2Mx2N),
// warp tile 64x32, 3 CTAs/SM, one barrier per K-step.
__global__ __launch_bounds__(128, 3) void gemm_kernel(const float* __restrict__ bias) {
    extern __shared__ char smem[];
    const uint32_t su = smem_u32(smem);
    const int tid  = threadIdx.x;
    const int lane = tid & 31;
    const int warp = tid >> 5;       // 0..3
    const int wm = warp >> 1;        // 0..1  (M)
    const int wn = warp & 1;         // 0..1  (N)
    const int cta_m = blockIdx.y * BM;
    const int cta_n = blockIdx.x * BN;

    float acc[4][4][4];              // [mt][nt][frag]
    #pragma unroll
    for (int a = 0; a < 4; a++)
        #pragma unroll
        for (int b = 0; b < 4; b++)
            #pragma unroll
            for (int c = 0; c < 4; c++) acc[a][b][c] = 0.0f;

    // ---- fragment smem offsets (128B rows; swizzle: chunk ^= row&7) ----
    const int sw = lane & 7;
    uint32_t aOff[4];
    #pragma unroll
    for (int mt = 0; mt < 4; mt++)
        aOff[mt] = (uint32_t)((wm * 64 + mt * 16 + (lane & 15)) * 128);
    const int aChunkHi = lane >> 4;
    uint32_t bOff[2];
    #pragma unroll
    for (int p = 0; p < 2; p++)
        bOff[p] = (uint32_t)((wn * 32 + p * 16 + ((lane >> 4) << 3) + (lane & 7)) * 128);
    const int bChunkHi = (lane >> 3) & 1;

    // ---- stage loader: 16B cp.async, swizzled, 128 threads ----
    const __nv_bfloat16* Ag = g_Abf + (size_t)cta_m * K_DIM;
    const __nv_bfloat16* Bg = g_Btbf + (size_t)cta_n * K_DIM;
    auto load_stage = [&](int kt) {
        const int st = kt % STAGES;
        const int k0 = kt * BK;
        const uint32_t aB = su + st * SM_STAGE;
        const uint32_t bB = aB + SM_A_STAGE;
        #pragma unroll
        for (int i = 0; i < 8; i++) {          // A: 1024 chunks / 128 thr
            int ch = tid + 128 * i;
            int row = ch >> 3, c = ch & 7;
            uint32_t dst = aB + row * 128 + ((c ^ (row & 7)) << 4);
            const void* src = Ag + (size_t)row * K_DIM + k0 + c * 8;
            asm volatile("cp.async.cg.shared.global [%0], [%1], 16;" :: "r"(dst), "l"(src));
        }
        #pragma unroll
        for (int i = 0; i < 4; i++) {          // B: 512 chunks / 128 thr
            int ch = tid + 128 * i;
            int row = ch >> 3, c = ch & 7;
            uint32_t dst = bB + row * 128 + ((c ^ (row & 7)) << 4);
            const void* src = Bg + (size_t)row * K_DIM + k0 + c * 8;
            asm volatile("cp.async.cg.shared.global [%0], [%1], 16;" :: "r"(dst), "l"(src));
        }
    };

    load_stage(0); asm volatile("cp.async.commit_group;");
    load_stage(1); asm volatile("cp.async.commit_group;");

    for (int kt = 0; kt < NKT; kt++) {
        if (kt + 1 < NKT) asm volatile("cp.async.wait_group 1;");
        else              asm volatile("cp.async.wait_group 0;");
        __syncthreads();   // orders stage-kt visibility AND protects stage (kt+2)%3 reuse

        if (kt + 2 < NKT) { load_stage(kt + 2); asm volatile("cp.async.commit_group;"); }

        const uint32_t stBase = su + (kt % STAGES) * SM_STAGE;
        const uint32_t bBase  = stBase + SM_A_STAGE;

        #pragma unroll
        for (int kk = 0; kk < 4; kk++) {
            uint32_t afr[4][4];
            #pragma unroll
            for (int mt = 0; mt < 4; mt++) {
                uint32_t addr = stBase + aOff[mt] + (((kk * 2 + aChunkHi) ^ sw) << 4);
                ldsm_x4(afr[mt], addr);
            }
            uint32_t bfr[2][4];
            #pragma unroll
            for (int p = 0; p < 2; p++) {
                uint32_t addr = bBase + bOff[p] + (((kk * 2 + bChunkHi) ^ sw) << 4);
                ldsm_x4(bfr[p], addr);
            }
            #pragma unroll
            for (int mt = 0; mt < 4; mt++) {
                #pragma unroll
                for (int p = 0; p < 2; p++) {
                    asm volatile(
                        "mma.sync.aligned.m16n8k16.row.col.f32.bf16.bf16.f32 "
                        "{%0,%1,%2,%3}, {%4,%5,%6,%7}, {%8,%9}, {%0,%1,%2,%3};\n"
                        : "+f"(acc[mt][2*p][0]), "+f"(acc[mt][2*p][1]),
                          "+f"(acc[mt][2*p][2]), "+f"(acc[mt][2*p][3])
                        : "r"(afr[mt][0]), "r"(afr[mt][1]), "r"(afr[mt][2]), "r"(afr[mt][3]),
                          "r"(bfr[p][0]), "r"(bfr[p][1]));
                    asm volatile(
                        "mma.sync.aligned.m16n8k16.row.col.f32.bf16.bf16.f32 "
                        "{%0,%1,%2,%3}, {%4,%5,%6,%7}, {%8,%9}, {%0,%1,%2,%3};\n"
                        : "+f"(acc[mt][2*p+1][0]), "+f"(acc[mt][2*p+1][1]),
                          "+f"(acc[mt][2*p+1][2]), "+f"(acc[mt][2*p+1][3])
                        : "r"(afr[mt][0]), "r"(afr[mt][1]), "r"(afr[mt][2]), "r"(afr[mt][3]),
                          "r"(bfr[p][2]), "r"(bfr[p][3]));
                }
            }
        }
    }

    // epilogue: add bias, write logits
    const int g = lane >> 2;
    const int t = lane & 3;
    #pragma unroll
    for (int mt = 0; mt < 4; mt++) {
        int row = cta_m + wm * 64 + mt * 16 + g;
        #pragma unroll
        for (int nt = 0; nt < 4; nt++) {
            int col = cta_n + wn * 32 + nt * 8 + 2 * t;
            float2 bv = *reinterpret_cast<const float2*>(bias + col);
            float2 v0 = make_float2(acc[mt][nt][0] + bv.x, acc[mt][nt][1] + bv.y);
            float2 v1 = make_float2(acc[mt][nt][2] + bv.x, acc[mt][nt][3] + bv.y);
            *reinterpret_cast<float2*>(g_logits + (size_t)row * N_DIM + col) = v0;
            *reinterpret_cast<float2*>(g_logits + (size_t)(row + 8) * N_DIM + col) = v1;
        }
    }
}

// ---------------- kernel 4: argmax + exact fp32 rescue + histogram ----------------
__global__ __launch_bounds__(256) void argmax_kernel(const float* __restrict__ hidden,
                                                     const float* __restrict__ bias) {
    const int lane = threadIdx.x & 31;
    const int gw = blockIdx.x * 8 + (threadIdx.x >> 5);
    const int r = gw >> 1;
    const int g = gw & 1;
    const float* base = g_logits + (size_t)r * N_DIM + g * NVARS;

    float v[10];
    float bestv = -INFINITY;
    int besti = 0x7fffffff;
    #pragma unroll
    for (int j = 0; j < 10; j++) {
        v[j] = base[lane + 32 * j];
        int idx = lane + 32 * j;
        if (v[j] > bestv) { bestv = v[j]; besti = idx; }
    }
    #pragma unroll
    for (int off = 16; off > 0; off >>= 1) {
        float ov = __shfl_down_sync(0xffffffffu, bestv, off);
        int   oi = __shfl_down_sync(0xffffffffu, besti, off);
        if (ov > bestv || (ov == bestv && oi < besti)) { bestv = ov; besti = oi; }
    }
    bestv = __shfl_sync(0xffffffffu, bestv, 0);
    besti = __shfl_sync(0xffffffffu, besti, 0);

    const float thr = bestv - MARGIN;
    unsigned masks[10];
    int ncand = 0;
    #pragma unroll
    for (int j = 0; j < 10; j++) {
        masks[j] = __ballot_sync(0xffffffffu, v[j] >= thr);
        ncand += __popc(masks[j]);
    }

    int final_idx = besti;
    if (ncand > 1) {
        const float* hrow = hidden + (size_t)r * K_DIM;
        float bexact = -INFINITY;
        int bidx = -1;
        for (int j = 0; j < 10; j++) {
            unsigned m = masks[j];
            while (m) {
                int l = __ffs(m) - 1;
                m &= m - 1;
                int col = l + 32 * j;
                const float* wrow = g_Wt + (size_t)(g * NVARS + col) * K_DIM;
                float s = 0.0f;
                for (int k = lane; k < K_DIM; k += 32)
                    s = fmaf(hrow[k], wrow[k], s);
                #pragma unroll
                for (int off = 16; off > 0; off >>= 1)
                    s += __shfl_xor_sync(0xffffffffu, s, off);
                s += bias[g * NVARS + col];
                if (s > bexact) { bexact = s; bidx = col; }
            }
        }
        final_idx = bidx;
    }

    if (lane == 0) {
        g_idx[r * 2 + g] = final_idx;
        atomicAdd(&g_counts[g * NVARS + final_idx], 1);
    }
}

// ---------------- kernel 5: gather codevectors ----------------
__global__ void gather_kernel(const float* __restrict__ cv, float* __restrict__ out) {
    int gid = blockIdx.x * blockDim.x + threadIdx.x;
    int r = gid >> 6;
    int q = gid & 63;
    int d = q * 4;
    const float* src;
    if (d < CVD) {
        int i0 = g_idx[r * 2];
        src = cv + ((size_t)i0 * CVD + d);
    } else {
        int i1 = g_idx[r * 2 + 1];
        src = cv + ((size_t)(NVARS + i1) * CVD + (d - CVD));
    }
    float4 val = *reinterpret_cast<const float4*>(src);
    *reinterpret_cast<float4*>(out + (size_t)r * 256 + d) = val;
}

// ---------------- kernel 6: perplexity ----------------
__global__ void ppl_kernel(float* __restrict__ out_scalar) {
    __shared__ float wsum[20];
    int tid = threadIdx.x;
    float m = (float)g_counts[tid] * (1.0f / 16384.0f);
    float term = m * logf(m + 1e-7f);
    #pragma unroll
    for (int off = 16; off > 0; off >>= 1)
        term += __shfl_xor_sync(0xffffffffu, term, off);
    if ((tid & 31) == 0) wsum[tid >> 5] = term;
    __syncthreads();
    if (tid == 0) {
        float s0 = 0.0f, s1 = 0.0f;
        #pragma unroll
        for (int w = 0; w < 10; w++) s0 += wsum[w];
        #pragma unroll
        for (int w = 10; w < 20; w++) s1 += wsum[w];
        *out_scalar = expf(-s0) + expf(-s1);
    }
}

// ---------------- launch ----------------
extern "C" void kernel_launch(void* const* d_in, const int* in_sizes, int n_in,
                              void* d_out, int out_size) {
    const float* hidden = (const float*)d_in[0];
    const float* W      = (const float*)d_in[1];
    const float* bias   = (const float*)d_in[2];
    const float* cv     = (const float*)d_in[3];
    float* out = (float*)d_out;

    cudaFuncSetAttribute(gemm_kernel, cudaFuncAttributeMaxDynamicSharedMemorySize, SM_TOTAL);

    const int convBlocks = (M_DIM * (K_DIM / 4)) / 256;
    // gemm kept as the 4th launch: ncu's deterministic skip profiles it
    conv_a_kernel<<<convBlocks / 2, 256>>>(hidden, 0);
    conv_a_kernel<<<convBlocks / 2, 256>>>(hidden, (convBlocks / 2) * 256);
    trans_w_kernel<<<dim3(N_DIM / 32, K_DIM / 32), 256>>>(W);
    gemm_kernel<<<dim3(N_DIM / BN, M_DIM / BM), 128, SM_TOTAL>>>(bias);
    argmax_kernel<<<(M_DIM * NGROUPS) / 8, 256>>>(hidden, bias);
    gather_kernel<<<(M_DIM * 64) / 256, 256>>>(cv, out);
    ppl_kernel<<<1, N_DIM>>>(out + (out_size - 1));
}